// round 1
// baseline (speedup 1.0000x reference)
#include <cuda_runtime.h>
#include <cstdint>
#include <cstddef>

typedef unsigned long long u64;

// ---- packed f32x2 helpers (Blackwell sm_103a) ----
#define FMA2(d, a, b, c) asm("fma.rn.f32x2 %0, %1, %2, %3;" : "=l"(d) : "l"(a), "l"(b), "l"(c))
#define MUL2(d, a, b)    asm("mul.rn.f32x2 %0, %1, %2;"     : "=l"(d) : "l"(a), "l"(b))

__device__ __forceinline__ u64 pack2(float lo, float hi) {
    u64 r; asm("mov.b64 %0, {%1, %2};" : "=l"(r) : "f"(lo), "f"(hi)); return r;
}
__device__ __forceinline__ float2 unpack2(u64 v) {
    float2 r; asm("mov.b64 {%0, %1}, %2;" : "=f"(r.x), "=f"(r.y) : "l"(v)); return r;
}

constexpr int E_DIM = 1024;   // embedding dim
constexpr int RPG   = 8;      // rows per group
constexpr int GPB   = 4;      // groups per block  -> 32 rows / block
constexpr int TPB   = 256;    // threads per block (8 warps)

// Fused: h = x @ w1^T + b1 ; c = cos(h) ; q = Pauli-Z-string products ; out = q @ w2^T + b2
// Quantum circuit (RX layer + 2x(CNOT ladder + H7)) reduces analytically to:
//   q0=c0, q1=c1, q2=c0c2, q3=c1c3, q4=c0c2c4, q5=c1c3c5, q6=c0c2c4c6, q7=prod(c0..c7)
__global__ void __launch_bounds__(TPB, 2)
ffq_kernel(const float* __restrict__ x,  const float* __restrict__ w1,
           const float* __restrict__ b1, const float* __restrict__ w2,
           const float* __restrict__ b2, float* __restrict__ out)
{
    __shared__ float  s_part[RPG][8][8];   // [row][f][warp] partial dot products
    __shared__ float2 s_q[RPG][8];         // q duplicated (q,q) for packed FMA

    const int tid  = threadIdx.x;
    const int warp = tid >> 5;
    const int lane = tid & 31;

    // ---------- phase-1 weights: warp owns e-slice [warp*128, warp*128+128) ----------
    const int e1 = warp * 128 + lane * 4;
    u64 wa[8], wb[8];
#pragma unroll
    for (int f = 0; f < 8; f++) {
        float4 v = *reinterpret_cast<const float4*>(w1 + f * E_DIM + e1);
        wa[f] = pack2(v.x, v.y);
        wb[f] = pack2(v.z, v.w);
    }

    // ---------- phase-2 weights: thread owns out columns e2..e2+3 ----------
    const int e2 = tid * 4;
    u64 p01[8], p23[8];
    {
        float we[4][8];
#pragma unroll
        for (int i = 0; i < 4; i++) {
            float4 lo = *reinterpret_cast<const float4*>(w2 + (e2 + i) * 8);
            float4 hi = *reinterpret_cast<const float4*>(w2 + (e2 + i) * 8 + 4);
            we[i][0] = lo.x; we[i][1] = lo.y; we[i][2] = lo.z; we[i][3] = lo.w;
            we[i][4] = hi.x; we[i][5] = hi.y; we[i][6] = hi.z; we[i][7] = hi.w;
        }
#pragma unroll
        for (int f = 0; f < 8; f++) {
            p01[f] = pack2(we[0][f], we[1][f]);
            p23[f] = pack2(we[2][f], we[3][f]);
        }
    }
    u64 b01, b23;
    {
        float4 bv = *reinterpret_cast<const float4*>(b2 + e2);
        b01 = pack2(bv.x, bv.y);
        b23 = pack2(bv.z, bv.w);
    }

    const int block_row0 = blockIdx.x * (RPG * GPB);

    for (int g = 0; g < GPB; g++) {
        const int row0 = block_row0 + g * RPG;

        // =================== phase 1: h partials ===================
        float4 xr[4];
#pragma unroll
        for (int r = 0; r < 4; r++)
            xr[r] = *reinterpret_cast<const float4*>(x + (size_t)(row0 + r) * E_DIM + e1);

#pragma unroll
        for (int r = 0; r < RPG; r++) {
            float4 xv = xr[r & 3];
            if (r < 4)  // rolling prefetch of rows 4..7
                xr[r & 3] = *reinterpret_cast<const float4*>(
                    x + (size_t)(row0 + r + 4) * E_DIM + e1);

            u64 xA = pack2(xv.x, xv.y);
            u64 xB = pack2(xv.z, xv.w);
            float s[8];
#pragma unroll
            for (int f = 0; f < 8; f++) {
                u64 acc;
                MUL2(acc, xA, wa[f]);
                FMA2(acc, xB, wb[f], acc);
                float2 t = unpack2(acc);
                s[f] = t.x + t.y;
            }
            // value-halving butterfly: 8 values over 32 lanes -> h[f] on lanes 4f
            {
                const bool hi = (lane & 16);
#pragma unroll
                for (int k = 0; k < 4; k++) {
                    float send = hi ? s[k]     : s[k + 4];
                    float keep = hi ? s[k + 4] : s[k];
                    s[k] = keep + __shfl_xor_sync(0xffffffffu, send, 16);
                }
            }
            {
                const bool hi = (lane & 8);
#pragma unroll
                for (int k = 0; k < 2; k++) {
                    float send = hi ? s[k]     : s[k + 2];
                    float keep = hi ? s[k + 2] : s[k];
                    s[k] = keep + __shfl_xor_sync(0xffffffffu, send, 8);
                }
            }
            {
                const bool hi = (lane & 4);
                float send = hi ? s[0] : s[1];
                float keep = hi ? s[1] : s[0];
                s[0] = keep + __shfl_xor_sync(0xffffffffu, send, 4);
            }
            s[0] += __shfl_xor_sync(0xffffffffu, s[0], 2);
            s[0] += __shfl_xor_sync(0xffffffffu, s[0], 1);

            if ((lane & 3) == 0)
                s_part[r][lane >> 2][warp] = s[0];  // f = (lane>>2)
        }
        __syncthreads();

        // =================== q computation (64 threads) ===================
        if (tid < 64) {
            const int r = tid >> 3;
            const int f = tid & 7;
            float h = b1[f];
#pragma unroll
            for (int w = 0; w < 8; w++) h += s_part[r][f][w];
            float c = cosf(h);

            // gather all 8 c's of this row (8 consecutive lanes) via shfl
            const int base = lane & 24;
            float cs[8];
#pragma unroll
            for (int j = 0; j < 8; j++)
                cs[j] = __shfl_sync(0xffffffffu, c, base + j);

            float q;
            if (f == 7) {
                q = cs[0]*cs[1]*cs[2]*cs[3]*cs[4]*cs[5]*cs[6]*cs[7];
            } else {
                q = 1.0f;
#pragma unroll
                for (int j = 0; j < 8; j++)
                    if (j <= f && ((j ^ f) & 1) == 0) q *= cs[j];
            }
            s_q[r][f] = make_float2(q, q);
        }
        __syncthreads();

        // =================== phase 2: out = q @ w2^T + b2 ===================
#pragma unroll
        for (int r = 0; r < RPG; r++) {
            u64 acc01 = b01, acc23 = b23;
#pragma unroll
            for (int f = 0; f < 8; f++) {
                u64 qq = *reinterpret_cast<const u64*>(&s_q[r][f]);  // LDS.64 broadcast
                FMA2(acc01, qq, p01[f], acc01);
                FMA2(acc23, qq, p23[f], acc23);
            }
            float2 a = unpack2(acc01);
            float2 b = unpack2(acc23);
            float4 o = make_float4(a.x, a.y, b.x, b.y);
            *reinterpret_cast<float4*>(out + (size_t)(row0 + r) * E_DIM + e2) = o;
        }
        __syncthreads();
    }
}

extern "C" void kernel_launch(void* const* d_in, const int* in_sizes, int n_in,
                              void* d_out, int out_size) {
    const float* x  = (const float*)d_in[0];
    const float* w1 = (const float*)d_in[1];
    const float* b1 = (const float*)d_in[2];
    const float* w2 = (const float*)d_in[3];
    const float* b2 = (const float*)d_in[4];
    float* out = (float*)d_out;

    const int rows   = in_sizes[0] / E_DIM;        // B*S = 32768
    const int blocks = rows / (RPG * GPB);         // 1024
    ffq_kernel<<<blocks, TPB>>>(x, w1, b1, w2, b2, out);
}